// round 17
// baseline (speedup 1.0000x reference)
#include <cuda_runtime.h>
#include <cuda_fp16.h>
#include <math.h>
#include <stdint.h>

// Problem constants
#define HIDDEN 2048
#define NHEAD  16
#define HDIM   128
#define BB     2
#define SSEQ   2048
#define BH     (BB * NHEAD)      // 32
#define MROWS  (BB * SSEQ)       // 4096

// ---------------- scratch (device globals; no allocation allowed) -----------
__device__ __align__(128) __half g_x  [(size_t)MROWS * HIDDEN];              // fp16
__device__ __align__(128) __half g_w3 [(size_t)3 * HIDDEN * HIDDEN];         // Wq|Wk|Wv
__device__ __align__(128) __half g_wo [(size_t)HIDDEN * HIDDEN];
__device__ __align__(128) float  g_b3 [3 * HIDDEN];                          // bq|bk|bv
__device__ __align__(128) __half g_q  [(size_t)BH * SSEQ * HDIM];  // [B,H,S,D]
__device__ __align__(128) __half g_k  [(size_t)BH * SSEQ * HDIM];
__device__ __align__(128) __half g_v  [(size_t)BH * SSEQ * HDIM];
__device__ __align__(128) __half g_ao [(size_t)MROWS * HIDDEN];

// ============================ PTX helpers ====================================
__device__ __forceinline__ uint32_t smem_to_u32(const void* smem_ptr) {
    uint32_t addr;
    asm("{ .reg .u64 tmp; cvta.to.shared.u64 tmp, %1; cvt.u32.u64 %0, tmp; }"
        : "=r"(addr) : "l"(smem_ptr));
    return addr;
}
#define CP_ASYNC16(smem_u32, gptr) \
    asm volatile("cp.async.cg.shared.global [%0], [%1], 16;" \
        :: "r"((uint32_t)(smem_u32)), "l"(gptr) : "memory")
#define CP_ASYNC_COMMIT() asm volatile("cp.async.commit_group;" ::: "memory")
#define CP_ASYNC_WAIT(n)  asm volatile("cp.async.wait_group %0;" :: "n"(n) : "memory")

__device__ __forceinline__ void ldsm4(uint32_t* r, uint32_t addr) {
    asm volatile("ldmatrix.sync.aligned.m8n8.x4.shared.b16 {%0,%1,%2,%3}, [%4];"
        : "=r"(r[0]), "=r"(r[1]), "=r"(r[2]), "=r"(r[3]) : "r"(addr));
}
__device__ __forceinline__ void ldsm4t(uint32_t* r, uint32_t addr) {
    asm volatile("ldmatrix.sync.aligned.m8n8.x4.trans.shared.b16 {%0,%1,%2,%3}, [%4];"
        : "=r"(r[0]), "=r"(r[1]), "=r"(r[2]), "=r"(r[3]) : "r"(addr));
}
// fp16 inputs, fp32 accumulate
__device__ __forceinline__ void mma16816(float* d, const uint32_t* a,
                                         uint32_t b0, uint32_t b1) {
    asm volatile(
        "mma.sync.aligned.m16n8k16.row.col.f32.f16.f16.f32 "
        "{%0,%1,%2,%3}, {%4,%5,%6,%7}, {%8,%9}, {%0,%1,%2,%3};"
        : "+f"(d[0]), "+f"(d[1]), "+f"(d[2]), "+f"(d[3])
        : "r"(a[0]), "r"(a[1]), "r"(a[2]), "r"(a[3]), "r"(b0), "r"(b1));
}
__device__ __forceinline__ float fast_exp2(float x) {
    float y;
    asm("ex2.approx.f32 %0, %1;" : "=f"(y) : "f"(x));
    return y;
}
__device__ __forceinline__ uint32_t pack_half2(float a, float b) {
    __half2 t; t.x = __float2half_rn(a); t.y = __float2half_rn(b);
    return *reinterpret_cast<uint32_t*>(&t);
}

// ===================== HMMA fp16 NT GEMM ====================================
// (unchanged from R16)  C = A @ B^T (+bias), fp32 accumulate.
// CTA 128x128, 4 warps of 64x64, K-chunk 32, XOR swizzle, 4-stage, 2 CTAs/SM.
#define TG_TILE     (128 * 64)              // 8192
#define TG_STAGE    (2 * TG_TILE)           // A, B = 16384
#define TG_SMEM     (4 * TG_STAGE)          // 65536 -> 2 CTAs/SM

__global__ void __launch_bounds__(128, 2)
tgemm_nt(const __half* __restrict__ A, const __half* __restrict__ B,
         const float* __restrict__ bias, int K, int Ntot, int mode,
         float* __restrict__ outF,
         __half* __restrict__ oq, __half* __restrict__ ok,
         __half* __restrict__ ov)
{
    extern __shared__ __align__(128) char smem[];
    const uint32_t sb = smem_to_u32(smem);

    const int tid  = threadIdx.x;
    const int lane = tid & 31;
    const int wid  = tid >> 5;          // 0..3
    const int wm   = wid >> 1;          // 0..1
    const int wn   = wid & 1;           // 0..1

    const int m0 = blockIdx.y * 128;
    const int n0 = blockIdx.x * 128;
    const int nch = K >> 5;             // K / 32

    const size_t aBase = (size_t)m0 * K;
    const size_t bBase = (size_t)n0 * K;

    float acc[4][8][4];
    #pragma unroll
    for (int i = 0; i < 4; i++)
        #pragma unroll
        for (int j = 0; j < 8; j++)
            #pragma unroll
            for (int t = 0; t < 4; t++) acc[i][j][t] = 0.0f;

    auto load_chunk = [&](int buf, int k0) {
        const uint32_t tb = sb + buf * TG_STAGE;
        #pragma unroll
        for (int ii = 0; ii < 4; ii++) {
            const int i = tid + ii * 128;        // 0..511
            const int r = i >> 2;                // row 0..127
            const int c = i & 3;                 // 16B chunk 0..3
            const uint32_t so = (uint32_t)(r * 64 + ((c ^ ((r >> 1) & 3)) << 4));
            const size_t aOff = aBase + (size_t)r * K + k0 + c * 8;
            const size_t bOff = bBase + (size_t)r * K + k0 + c * 8;
            CP_ASYNC16(tb + 0 * TG_TILE + so, (const char*)(A + aOff));
            CP_ASYNC16(tb + 1 * TG_TILE + so, (const char*)(B + bOff));
        }
        CP_ASYNC_COMMIT();
    };

    const int hiA = lane >> 4;
    const int swA = ((lane & 15) >> 1) & 3;
    const uint32_t aRowOff = (uint32_t)((wm * 64 + (lane & 15)) * 64);
    const int hiB = (lane >> 3) & 1;
    const int swB = ((lane & 7) >> 1) & 3;
    const uint32_t bRowOff = (uint32_t)((wn * 64 + (lane & 7) + ((lane >> 4) & 1) * 8) * 64);

    load_chunk(0, 0);
    if (nch > 1) load_chunk(1, 32);
    if (nch > 2) load_chunk(2, 64);

    for (int c = 0; c < nch; c++) {
        const int buf = c & 3;
        if (c + 2 < nch)      { CP_ASYNC_WAIT(2); }
        else if (c + 1 < nch) { CP_ASYNC_WAIT(1); }
        else                  { CP_ASYNC_WAIT(0); }
        __syncthreads();
        if (c + 3 < nch) load_chunk((c + 3) & 3, (c + 3) * 32);

        const uint32_t tb = sb + buf * TG_STAGE;
        const uint32_t tA = tb + 0 * TG_TILE + aRowOff;
        const uint32_t tB = tb + 1 * TG_TILE + bRowOff;

        #pragma unroll
        for (int ks = 0; ks < 2; ks++) {
            const uint32_t koA = (uint32_t)(((ks * 2 + hiA) ^ swA) << 4);
            const uint32_t koB = (uint32_t)(((ks * 2 + hiB) ^ swB) << 4);
            uint32_t a[4][4], bh[4][4];
            #pragma unroll
            for (int mt = 0; mt < 4; mt++) ldsm4(a[mt], tA + mt * (16 * 64) + koA);
            #pragma unroll
            for (int nt = 0; nt < 4; nt++) ldsm4(bh[nt], tB + nt * (16 * 64) + koB);
            #pragma unroll
            for (int mi = 0; mi < 4; mi++)
                #pragma unroll
                for (int ni = 0; ni < 8; ni++) {
                    const int g = ni >> 1, o = (ni & 1) * 2;
                    mma16816(acc[mi][ni], a[mi], bh[g][o], bh[g][o + 1]);
                }
        }
    }

    const int gid = lane >> 2;
    const int tig = lane & 3;

    auto storePair = [&](int m, int n, float v0, float v1) {
        if (bias) { v0 += bias[n]; v1 += bias[n + 1]; }
        if (mode == 0) {
            float2 t; t.x = v0; t.y = v1;
            *reinterpret_cast<float2*>(&outF[(size_t)m * Ntot + n]) = t;
        } else {
            const int p  = n >> 11;                 // 0=q, 1=k, 2=v
            const int n2 = n & (HIDDEN - 1);
            const int b = m >> 11, s = m & (SSEQ - 1);
            const int h = n2 >> 7, d = n2 & (HDIM - 1);
            const size_t idx = (((size_t)(b * NHEAD + h) * SSEQ) + s) * HDIM + d;
            __half2 th;
            th.x = __float2half_rn(v0);
            th.y = __float2half_rn(v1);
            __half* dst = (p == 0) ? oq : ((p == 1) ? ok : ov);
            *reinterpret_cast<__half2*>(&dst[idx]) = th;
        }
    };

    #pragma unroll
    for (int mi = 0; mi < 4; mi++) {
        #pragma unroll
        for (int ni = 0; ni < 8; ni++) {
            const int m = m0 + wm * 64 + mi * 16 + gid;
            const int n = n0 + wn * 64 + ni * 8 + tig * 2;
            storePair(m,     n, acc[mi][ni][0], acc[mi][ni][1]);
            storePair(m + 8, n, acc[mi][ni][2], acc[mi][ni][3]);
        }
    }
}

// ===================== fused flash attention (plain fp16) ===================
// 128 q-rows/CTA, 4 warps x 32 rows (halves K/V smem duplication per MAC),
// 32-key stages, 4-stage ring, 2 CTAs/SM, Q in registers, log2 softmax.
#define FA_STRIDE  272                       // 128 fp16 + 8 pad
#define FA_KVTILE  (32 * FA_STRIDE)          // 8704
#define FA_STAGE   (2 * FA_KVTILE)           // K, V = 17408
#define FA_SMEM    (4 * FA_STAGE)            // 69632 -> 2 CTAs/SM
#define FA_QBYTES  (128 * FA_STRIDE)         // 34816 = 2 stages

__global__ void __launch_bounds__(128, 2)
fa_kernel(const __half* __restrict__ q,
          const __half* __restrict__ k, const __half* __restrict__ v,
          const float* __restrict__ mask, __half* __restrict__ ao)
{
    extern __shared__ __align__(128) char smem[];
    const uint32_t sStg = smem_to_u32(smem);

    const int tid  = threadIdx.x;
    const int lane = tid & 31;
    const int wid  = tid >> 5;           // 0..3
    const int gid  = lane >> 2;
    const int tig  = lane & 3;

    const int z  = blockIdx.y;
    const int q0 = blockIdx.x * 128;
    const int b  = z >> 4;
    const int h  = z & (NHEAD - 1);

    const size_t qBase  = ((size_t)z * SSEQ + q0) * HDIM;
    const size_t kvBase = (size_t)z * SSEQ * HDIM;

    // ---- Q tile (128 rows) staged into stages 2..3, then to registers
    const uint32_t sQ = sStg + 2 * FA_STAGE;
    #pragma unroll
    for (int ii = 0; ii < 16; ii++) {
        const int i = tid + ii * 128;            // 0..2047
        const int r = i >> 4;                    // 0..127
        const int c = i & 15;
        const uint32_t so = (uint32_t)(r * FA_STRIDE + c * 16);
        const size_t go = qBase + (size_t)r * HDIM + c * 8;
        CP_ASYNC16(sQ + so, (const char*)(q + go));
    }
    CP_ASYNC_COMMIT();                       // group: Q

    auto load_stage = [&](int st, int k0) {
        const uint32_t tb = sStg + st * FA_STAGE;
        #pragma unroll
        for (int ii = 0; ii < 4; ii++) {
            const int i = tid + ii * 128;        // 0..511
            const int r = i >> 4;                // 0..31
            const int c = i & 15;
            const uint32_t so = (uint32_t)(r * FA_STRIDE + c * 16);
            const size_t go = kvBase + (size_t)(k0 + r) * HDIM + c * 8;
            CP_ASYNC16(tb + 0 * FA_KVTILE + so, (const char*)(k + go));
            CP_ASYNC16(tb + 1 * FA_KVTILE + so, (const char*)(v + go));
        }
        CP_ASYNC_COMMIT();
    };
    load_stage(0, 0);                        // group: s0

    // wait Q (s0 may pend), move Q to registers, then free the staging area
    uint32_t qA[2][8][4];
    CP_ASYNC_WAIT(1);
    __syncthreads();
    #pragma unroll
    for (int mt = 0; mt < 2; mt++) {
        const uint32_t aOff = (uint32_t)((32 * wid + mt * 16 + (lane & 15)) * FA_STRIDE
                                         + (lane >> 4) * 16);
        #pragma unroll
        for (int kd = 0; kd < 8; kd++)
            ldsm4(qA[mt][kd], sQ + aOff + kd * 32);
    }
    __syncthreads();                         // all warps done with Q area
    load_stage(1, 32);                       // overwrites part of Q area: safe
    load_stage(2, 64);

    float O[2][16][4];
    #pragma unroll
    for (int mt = 0; mt < 2; mt++)
        #pragma unroll
        for (int i = 0; i < 16; i++)
            #pragma unroll
            for (int j = 0; j < 4; j++) O[mt][i][j] = 0.0f;
    float mm[2][2], ll[2][2];
    #pragma unroll
    for (int mt = 0; mt < 2; mt++) {
        mm[mt][0] = -1e30f; mm[mt][1] = -1e30f;
        ll[mt][0] = 0.0f;   ll[mt][1] = 0.0f;
    }

    const uint32_t bOff = (uint32_t)(((lane & 7) + ((lane >> 4) & 1) * 8) * FA_STRIDE
                                     + ((lane >> 3) & 1) * 16);
    const uint32_t vOff = (uint32_t)(((lane & 7) + ((lane >> 3) & 1) * 8) * FA_STRIDE
                                     + ((lane >> 4) & 1) * 16);
    const float* mrow = mask + (size_t)b * SSEQ;
    const float LOG2E  = 1.4426950408889634f;
    const float scale2 = 0.08838834764831845f * LOG2E;   // (1/sqrt(128))*log2(e)

    for (int c = 0; c < 64; c++) {
        if (c + 2 < 64)      { CP_ASYNC_WAIT(2); }
        else if (c + 1 < 64) { CP_ASYNC_WAIT(1); }
        else                 { CP_ASYNC_WAIT(0); }
        __syncthreads();
        if (c + 3 < 64) load_stage((c + 3) & 3, (c + 3) * 32);

        const uint32_t tb = sStg + (uint32_t)(c & 3) * FA_STAGE;
        const int k0 = c * 32;

        float S[2][4][4];
        #pragma unroll
        for (int mt = 0; mt < 2; mt++)
            #pragma unroll
            for (int i = 0; i < 4; i++)
                #pragma unroll
                for (int j = 0; j < 4; j++) S[mt][i][j] = 0.0f;

        #pragma unroll
        for (int kd = 0; kd < 8; kd++) {
            #pragma unroll
            for (int np = 0; np < 2; np++) {
                uint32_t bH[4];
                ldsm4(bH, tb + 0 * FA_KVTILE + bOff + np * (16 * FA_STRIDE) + kd * 32);
                #pragma unroll
                for (int mt = 0; mt < 2; mt++) {
                    mma16816(S[mt][2 * np],     qA[mt][kd], bH[0], bH[1]);
                    mma16816(S[mt][2 * np + 1], qA[mt][kd], bH[2], bH[3]);
                }
            }
        }

        // ---- scale + mask (log2 domain)
        #pragma unroll
        for (int nt = 0; nt < 4; nt++) {
            const float2 mv = *reinterpret_cast<const float2*>(mrow + k0 + nt * 8 + 2 * tig);
            const float mx2 = mv.x * LOG2E;
            const float my2 = mv.y * LOG2E;
            #pragma unroll
            for (int mt = 0; mt < 2; mt++) {
                S[mt][nt][0] = fmaf(S[mt][nt][0], scale2, mx2);
                S[mt][nt][1] = fmaf(S[mt][nt][1], scale2, my2);
                S[mt][nt][2] = fmaf(S[mt][nt][2], scale2, mx2);
                S[mt][nt][3] = fmaf(S[mt][nt][3], scale2, my2);
            }
        }

        // ---- online softmax per m-tile
        #pragma unroll
        for (int mt = 0; mt < 2; mt++) {
            float mx0 = -1e30f, mx1 = -1e30f;
            #pragma unroll
            for (int nt = 0; nt < 4; nt++) {
                mx0 = fmaxf(mx0, fmaxf(S[mt][nt][0], S[mt][nt][1]));
                mx1 = fmaxf(mx1, fmaxf(S[mt][nt][2], S[mt][nt][3]));
            }
            mx0 = fmaxf(mx0, __shfl_xor_sync(0xFFFFFFFFu, mx0, 1));
            mx0 = fmaxf(mx0, __shfl_xor_sync(0xFFFFFFFFu, mx0, 2));
            mx1 = fmaxf(mx1, __shfl_xor_sync(0xFFFFFFFFu, mx1, 1));
            mx1 = fmaxf(mx1, __shfl_xor_sync(0xFFFFFFFFu, mx1, 2));

            const float nm0 = fmaxf(mm[mt][0], mx0);
            const float nm1 = fmaxf(mm[mt][1], mx1);
            const float ef0 = fast_exp2(mm[mt][0] - nm0);
            const float ef1 = fast_exp2(mm[mt][1] - nm1);

            float rs0 = 0.0f, rs1 = 0.0f;
            #pragma unroll
            for (int nt = 0; nt < 4; nt++) {
                S[mt][nt][0] = fast_exp2(S[mt][nt][0] - nm0);
                S[mt][nt][1] = fast_exp2(S[mt][nt][1] - nm0);
                S[mt][nt][2] = fast_exp2(S[mt][nt][2] - nm1);
                S[mt][nt][3] = fast_exp2(S[mt][nt][3] - nm1);
                rs0 += S[mt][nt][0] + S[mt][nt][1];
                rs1 += S[mt][nt][2] + S[mt][nt][3];
            }
            rs0 += __shfl_xor_sync(0xFFFFFFFFu, rs0, 1);
            rs0 += __shfl_xor_sync(0xFFFFFFFFu, rs0, 2);
            rs1 += __shfl_xor_sync(0xFFFFFFFFu, rs1, 1);
            rs1 += __shfl_xor_sync(0xFFFFFFFFu, rs1, 2);

            ll[mt][0] = ll[mt][0] * ef0 + rs0;
            ll[mt][1] = ll[mt][1] * ef1 + rs1;
            mm[mt][0] = nm0; mm[mt][1] = nm1;

            #pragma unroll
            for (int nt = 0; nt < 16; nt++) {
                O[mt][nt][0] *= ef0; O[mt][nt][1] *= ef0;
                O[mt][nt][2] *= ef1; O[mt][nt][3] *= ef1;
            }
        }

        // ---- P (fp16) @ V (fp16), V ldsm shared across m-tiles
        #pragma unroll
        for (int ks = 0; ks < 2; ks++) {
            uint32_t paH[2][4];
            #pragma unroll
            for (int mt = 0; mt < 2; mt++) {
                #pragma unroll
                for (int qq = 0; qq < 2; qq++) {
                    const float* s4 = S[mt][2 * ks + qq];
                    paH[mt][qq * 2 + 0] = pack_half2(s4[0], s4[1]);
                    paH[mt][qq * 2 + 1] = pack_half2(s4[2], s4[3]);
                }
            }
            #pragma unroll
            for (int ntp = 0; ntp < 8; ntp++) {
                uint32_t vH[4];
                ldsm4t(vH, tb + 1 * FA_KVTILE + vOff + ks * (16 * FA_STRIDE) + ntp * 32);
                #pragma unroll
                for (int mt = 0; mt < 2; mt++) {
                    mma16816(O[mt][2 * ntp],     paH[mt], vH[0], vH[1]);
                    mma16816(O[mt][2 * ntp + 1], paH[mt], vH[2], vH[3]);
                }
            }
        }
    }

    // ---- epilogue
    #pragma unroll
    for (int mt = 0; mt < 2; mt++) {
        const float inv0 = 1.0f / ll[mt][0];
        const float inv1 = 1.0f / ll[mt][1];
        const int r0 = q0 + 32 * wid + mt * 16 + gid;
        const int r1 = r0 + 8;
        #pragma unroll
        for (int nt = 0; nt < 16; nt++) {
            const int d = h * HDIM + nt * 8 + 2 * tig;
            const size_t i0 = ((size_t)b * SSEQ + r0) * HIDDEN + d;
            const size_t i1 = ((size_t)b * SSEQ + r1) * HIDDEN + d;
            __half2 t0, t1;
            t0.x = __float2half_rn(O[mt][nt][0] * inv0);
            t0.y = __float2half_rn(O[mt][nt][1] * inv0);
            t1.x = __float2half_rn(O[mt][nt][2] * inv1);
            t1.y = __float2half_rn(O[mt][nt][3] * inv1);
            *reinterpret_cast<__half2*>(&ao[i0]) = t0;
            *reinterpret_cast<__half2*>(&ao[i1]) = t1;
        }
    }
}

// ===================== fp32 -> fp16 conversions =============================
__global__ void __launch_bounds__(256)
cvt_fp16(const float* __restrict__ in, __half* __restrict__ out, int n4)
{
    const int i = blockIdx.x * 256 + threadIdx.x;
    if (i >= n4) return;
    const float4 v = reinterpret_cast<const float4*>(in)[i];
    union { __half b[4]; uint2 u; } H;
    H.b[0] = __float2half_rn(v.x);
    H.b[1] = __float2half_rn(v.y);
    H.b[2] = __float2half_rn(v.z);
    H.b[3] = __float2half_rn(v.w);
    reinterpret_cast<uint2*>(out)[i] = H.u;
}

// 4 weight matrices in one launch: blockIdx.y selects Wq/Wk/Wv/Wo.
__global__ void __launch_bounds__(256)
cvt_fp16_w4(const float* __restrict__ w0, const float* __restrict__ w1,
            const float* __restrict__ w2, const float* __restrict__ w3,
            __half* __restrict__ w3o, __half* __restrict__ woo, int n4)
{
    const int i = blockIdx.x * 256 + threadIdx.x;
    if (i >= n4) return;
    const int p = blockIdx.y;
    const float* in = (p == 0) ? w0 : (p == 1) ? w1 : (p == 2) ? w2 : w3;
    const size_t wOff = (size_t)HIDDEN * HIDDEN / 4;   // in uint2 units
    __half* dst;
    size_t o;
    if (p < 3) { dst = w3o; o = (size_t)p * wOff; }
    else       { dst = woo; o = 0; }

    const float4 v = reinterpret_cast<const float4*>(in)[i];
    union { __half b[4]; uint2 u; } H;
    H.b[0] = __float2half_rn(v.x);
    H.b[1] = __float2half_rn(v.y);
    H.b[2] = __float2half_rn(v.z);
    H.b[3] = __float2half_rn(v.w);
    reinterpret_cast<uint2*>(dst)[o + i] = H.u;
}

// bias concat: [bq | bk | bv]
__global__ void __launch_bounds__(256)
concat_bias(const float* __restrict__ a, const float* __restrict__ b,
            const float* __restrict__ c, float* __restrict__ o)
{
    const int i = blockIdx.x * 256 + threadIdx.x;
    if (i < HIDDEN)          o[i] = a[i];
    else if (i < 2 * HIDDEN) o[i] = b[i - HIDDEN];
    else if (i < 3 * HIDDEN) o[i] = c[i - 2 * HIDDEN];
}

// ---------------------------------------------------------------------------
extern "C" void kernel_launch(void* const* d_in, const int* in_sizes, int n_in,
                              void* d_out, int out_size)
{
    (void)in_sizes; (void)n_in; (void)out_size;
    const float* x    = (const float*)d_in[0];
    const float* mask = (const float*)d_in[1];
    const float* Wq   = (const float*)d_in[2];
    const float* bq   = (const float*)d_in[3];
    const float* Wk   = (const float*)d_in[4];
    const float* bk   = (const float*)d_in[5];
    const float* Wv   = (const float*)d_in[6];
    const float* bv   = (const float*)d_in[7];
    const float* Wo   = (const float*)d_in[8];
    const float* bo   = (const float*)d_in[9];
    float* out = (float*)d_out;

    __half *xs, *w3, *wo, *qs, *ks, *vs, *aos;
    float* b3;
    cudaGetSymbolAddress((void**)&xs,  g_x);
    cudaGetSymbolAddress((void**)&w3,  g_w3);
    cudaGetSymbolAddress((void**)&wo,  g_wo);
    cudaGetSymbolAddress((void**)&b3,  g_b3);
    cudaGetSymbolAddress((void**)&qs,  g_q);
    cudaGetSymbolAddress((void**)&ks,  g_k);
    cudaGetSymbolAddress((void**)&vs,  g_v);
    cudaGetSymbolAddress((void**)&aos, g_ao);

    cudaFuncSetAttribute(tgemm_nt, cudaFuncAttributeMaxDynamicSharedMemorySize,
                         TG_SMEM);
    cudaFuncSetAttribute(fa_kernel, cudaFuncAttributeMaxDynamicSharedMemorySize,
                         FA_SMEM);

    // ---- conversions
    const int nX4 = (MROWS * HIDDEN) / 4;
    const int nW4 = (HIDDEN * HIDDEN) / 4;
    cvt_fp16<<<nX4 / 256, 256>>>(x, xs, nX4);
    cvt_fp16_w4<<<dim3(nW4 / 256, 4), 256>>>(Wq, Wk, Wv, Wo, w3, wo, nW4);
    concat_bias<<<(3 * HIDDEN) / 256, 256>>>(bq, bk, bv, b3);

    // ---- fused QKV projection -> q, k, v single fp16 [B,H,S,D]
    const dim3 gQKV(3 * HIDDEN / 128, MROWS / 128, 1);   // (48, 32)
    tgemm_nt<<<gQKV, 128, TG_SMEM>>>(xs, w3, b3, HIDDEN, 3 * HIDDEN, 1,
                                     nullptr, qs, ks, vs);

    // ---- fused attention -> AO single fp16 [B,S,HIDDEN]
    const dim3 gFA(SSEQ / 128, BH, 1);   // (16, 32) = 512 CTAs
    fa_kernel<<<gFA, 128, FA_SMEM>>>(qs, ks, vs, mask, aos);

    // ---- output projection (+bias) -> d_out
    const dim3 gO(HIDDEN / 128, MROWS / 128, 1);
    tgemm_nt<<<gO, 128, TG_SMEM>>>(aos, wo, bo, HIDDEN, HIDDEN, 0,
                                   out, nullptr, nullptr, nullptr);
}